// round 3
// baseline (speedup 1.0000x reference)
#include <cuda_runtime.h>
#include <math.h>

#define FULLMASK 0xFFFFFFFFu

// ---------------- scratch (device globals; allocation-free) ----------------
// global pixel index space: scales concatenated, PIXOFF = {0,2097152,2621440,2752512,2785280}, total 2793472
__device__ __align__(16) float g_amean[2793472];
__device__ __align__(16) float g_amax [2793472];
__device__ __align__(16) float g_sa   [2793472];
__device__ float g_part[32 * 128 * 32];   // per-(b, cglobal, tile) partial sums of t*(1+sa)
__device__ float g_catt[32 * 128];        // channel attention per (b, cglobal)

__device__ __forceinline__ float sigmoidf_(float x) {
    return 1.0f / (1.0f + __expf(-x));
}

// ---------------- Kernel 1: channel mean/max per pixel ----------------
// one thread = 4 consecutive pixels (float4), grid exact: 698368 quads
__global__ __launch_bounds__(256) void k_chanreduce(
    const float* __restrict__ t0, const float* __restrict__ t1,
    const float* __restrict__ t2, const float* __restrict__ t3,
    const float* __restrict__ t4)
{
    int q = blockIdx.x * 256 + threadIdx.x;          // quad index
    int pix = q * 4;                                  // global pixel index
    const float* tp; int C, l2, hw, chw, poff;
    if (q < 524288)      { tp = t0; C = 8;  l2 = 16; hw = 65536; chw = 524288; poff = 0;       }
    else if (q < 655360) { tp = t1; C = 16; l2 = 14; hw = 16384; chw = 262144; poff = 2097152; }
    else if (q < 688128) { tp = t2; C = 24; l2 = 12; hw = 4096;  chw = 98304;  poff = 2621440; }
    else if (q < 696320) { tp = t3; C = 32; l2 = 10; hw = 1024;  chw = 32768;  poff = 2752512; }
    else                 { tp = t4; C = 48; l2 = 8;  hw = 256;   chw = 12288;  poff = 2785280; }
    int p    = pix - poff;
    int b    = p >> l2;
    int hwid = p & (hw - 1);
    const float4* base = (const float4*)(tp + (size_t)b * chw + hwid);
    int cs = hw >> 2;                                  // channel stride in float4s
    float4 v = base[0];
    float4 s = v, m = v;
    for (int c = 1; c < C; c++) {
        v = base[(size_t)c * cs];
        s.x += v.x; s.y += v.y; s.z += v.z; s.w += v.w;
        m.x = fmaxf(m.x, v.x); m.y = fmaxf(m.y, v.y);
        m.z = fmaxf(m.z, v.z); m.w = fmaxf(m.w, v.w);
    }
    float inv = 1.0f / (float)C;
    s.x *= inv; s.y *= inv; s.z *= inv; s.w *= inv;
    *(float4*)(g_amean + pix) = s;
    *(float4*)(g_amax  + pix) = m;
}

// ---------------- Kernel 2 (FUSED): dilated 7x7 conv + sigmoid -> sa,
//                  then per-tile pooled partials of t*(1+sa) per channel ----------------
// block = 256 threads, output tile 64(h) x 32(w); thread = 8 consecutive output rows, 1 col.
// smem input tile: 82 rows x 50 cols per map. Register row-cache amortizes LDS.
// After conv, the block streams t over its tile for all C channels and writes one
// deterministic partial per (b, c, tile) to g_part (no atomics).
__global__ __launch_bounds__(256) void k_spconv_pool(
    const float* __restrict__ spw, const float* __restrict__ spb,
    const float* __restrict__ t0, const float* __restrict__ t1,
    const float* __restrict__ t2, const float* __restrict__ t3,
    const float* __restrict__ t4)
{
    __shared__ float sm[82 * 50];
    __shared__ float sx[82 * 50];
    __shared__ float wsh[98];
    __shared__ float ws8[8];
    int bx = blockIdx.x;
    const float* tp; int HD, hw, poff, tw, per, C, chw, cstart;
    if (bx < 1024)      { tp = t0; HD = 256; hw = 65536; poff = 0;       tw = 8; per = 32; C = 8;  chw = 524288; cstart = 0;  }
    else if (bx < 1280) { tp = t1; HD = 128; hw = 16384; poff = 2097152; tw = 4; per = 8;  C = 16; chw = 262144; cstart = 8;  bx -= 1024; }
    else if (bx < 1344) { tp = t2; HD = 64;  hw = 4096;  poff = 2621440; tw = 2; per = 2;  C = 24; chw = 98304;  cstart = 24; bx -= 1280; }
    else if (bx < 1376) { tp = t3; HD = 32;  hw = 1024;  poff = 2752512; tw = 1; per = 1;  C = 32; chw = 32768;  cstart = 48; bx -= 1344; }
    else                { tp = t4; HD = 16;  hw = 256;   poff = 2785280; tw = 1; per = 1;  C = 48; chw = 12288;  cstart = 80; bx -= 1376; }
    int b = bx / per, tile = bx % per;
    int tyb = tile / tw, txb = tile % tw;
    int y0 = tyb * 64, x0 = txb * 32;
    int tid = threadIdx.x;
    if (tid < 98) wsh[tid] = spw[tid];                 // [0..48]=mean w, [49..97]=max w
    int pb = poff + b * hw;
    for (int idx = tid; idx < 82 * 50; idx += 256) {
        int rr = idx / 50, cc = idx % 50;
        int gy = y0 - 9 + rr, gx = x0 - 9 + cc;
        float vm = 0.f, vx = 0.f;
        if ((unsigned)gy < (unsigned)HD && (unsigned)gx < (unsigned)HD) {
            int gi = pb + gy * HD + gx;
            vm = g_amean[gi]; vx = g_amax[gi];
        }
        sm[idx] = vm; sx[idx] = vx;
    }
    __syncthreads();

    int ty = tid >> 5, tx = tid & 31;                  // warp = one ty row-group
    int gx = x0 + tx;
    float acc[8];
#pragma unroll
    for (int d = 0; d < 8; d++) acc[d] = 0.f;
    int rbase = ty * 8;
#pragma unroll
    for (int kw = 0; kw < 7; kw++) {
        int cc = tx + 3 * kw;
        float cm[26], cx[26];
#pragma unroll
        for (int j = 0; j < 26; j++) {
            cm[j] = sm[(rbase + j) * 50 + cc];
            cx[j] = sx[(rbase + j) * 50 + cc];
        }
#pragma unroll
        for (int kh = 0; kh < 7; kh++) {
            float wm = wsh[kh * 7 + kw];
            float wx = wsh[49 + kh * 7 + kw];
#pragma unroll
            for (int d = 0; d < 8; d++)
                acc[d] += cm[d + 3 * kh] * wm + cx[d + 3 * kh] * wx;
        }
    }
    float bias = spb[0];
    float sval[8];                                     // 1 + sigmoid(conv), kept in regs for pooling
#pragma unroll
    for (int d = 0; d < 8; d++) sval[d] = 1.f + sigmoidf_(acc[d] + bias);
    if (gx < HD) {
#pragma unroll
        for (int d = 0; d < 8; d++) {
            int gy = y0 + rbase + d;
            if (gy < HD)
                g_sa[pb + gy * HD + gx] = sval[d] - 1.f;
        }
    }

    // ---- fused pooling: partial_c = sum over tile of t*(1+sa) ----
    for (int c = 0; c < C; c++) {
        float p = 0.f;
        if (gx < HD) {
            const float* tc = tp + (size_t)b * chw + (size_t)c * hw + gx;
#pragma unroll
            for (int d = 0; d < 8; d++) {
                int gy = y0 + rbase + d;
                if (gy < HD) p += tc[(size_t)gy * HD] * sval[d];
            }
        }
        for (int o = 16; o; o >>= 1) p += __shfl_down_sync(FULLMASK, p, o);
        if ((tid & 31) == 0) ws8[tid >> 5] = p;
        __syncthreads();
        if (tid == 0) {
            float tot = 0.f;
#pragma unroll
            for (int w = 0; w < 8; w++) tot += ws8[w];
            g_part[(b * 128 + cstart + c) * 32 + tile] = tot;
        }
        __syncthreads();
    }
}

// ---------------- Kernel 4: 1D conv over pooled + per-scale FC + sigmoid -> catt ----------------
// fully-unrolled float4 dot with 4 independent accumulators (MLP ~32)
__global__ __launch_bounds__(128) void k_att(
    const float* __restrict__ c1d,
    const float* __restrict__ w0, const float* __restrict__ bb0,
    const float* __restrict__ w1, const float* __restrict__ bb1,
    const float* __restrict__ w2, const float* __restrict__ bb2,
    const float* __restrict__ w3, const float* __restrict__ bb3,
    const float* __restrict__ w4, const float* __restrict__ bb4)
{
    int b = blockIdx.x;
    int j = threadIdx.x;
    int ntile, hw, c_; const float* wp; const float* bp;
    if (j < 8)       { ntile = 32; hw = 65536; wp = w0; bp = bb0; c_ = j;      }
    else if (j < 24) { ntile = 8;  hw = 16384; wp = w1; bp = bb1; c_ = j - 8;  }
    else if (j < 48) { ntile = 2;  hw = 4096;  wp = w2; bp = bb2; c_ = j - 24; }
    else if (j < 80) { ntile = 1;  hw = 1024;  wp = w3; bp = bb3; c_ = j - 48; }
    else             { ntile = 1;  hw = 256;   wp = w4; bp = bb4; c_ = j - 80; }
    float pv = 0.f;
    for (int k = 0; k < ntile; k++) pv += g_part[(b * 128 + j) * 32 + k];
    pv /= (float)hw;
    __shared__ float psh[128];
    __shared__ __align__(16) float ash[128];
    psh[j] = pv;
    __syncthreads();
    float a = c1d[1] * psh[j];
    if (j > 0)   a += c1d[0] * psh[j - 1];
    if (j < 127) a += c1d[2] * psh[j + 1];
    ash[j] = a;
    __syncthreads();

    const float4* wv = (const float4*)(wp + c_ * 128);
    const float4* av = (const float4*)ash;
    float s0 = 0.f, s1 = 0.f, s2 = 0.f, s3 = 0.f;
#pragma unroll
    for (int k = 0; k < 32; k += 4) {
        float4 wa = wv[k + 0], wb = wv[k + 1], wc = wv[k + 2], wd = wv[k + 3];
        float4 xa = av[k + 0], xb = av[k + 1], xc = av[k + 2], xd = av[k + 3];
        s0 += wa.x * xa.x + wa.y * xa.y + wa.z * xa.z + wa.w * xa.w;
        s1 += wb.x * xb.x + wb.y * xb.y + wb.z * xb.z + wb.w * xb.w;
        s2 += wc.x * xc.x + wc.y * xc.y + wc.z * xc.z + wc.w * xc.w;
        s3 += wd.x * xd.x + wd.y * xd.y + wd.z * xd.z + wd.w * xd.w;
    }
    float dot = bp[c_] + ((s0 + s1) + (s2 + s3));
    g_catt[b * 128 + j] = sigmoidf_(dot);
}

// ---------------- Kernel 5: out = t * (catt + sa*(1+catt)) ----------------
__global__ __launch_bounds__(256) void k_out(
    const float* __restrict__ t0, const float* __restrict__ t1,
    const float* __restrict__ t2, const float* __restrict__ t3,
    const float* __restrict__ t4, float* __restrict__ out)
{
    int q = blockIdx.x * 256 + threadIdx.x;            // quad index, exact 7438336
    const float* tp; int chw, l2, hw, poff, cstart, toff4;
    if (q < 4194304)      { tp = t0; chw = 524288; l2 = 16; hw = 65536; poff = 0;       cstart = 0;  toff4 = 0;       }
    else if (q < 6291456) { tp = t1; chw = 262144; l2 = 14; hw = 16384; poff = 2097152; cstart = 8;  toff4 = 4194304; }
    else if (q < 7077888) { tp = t2; chw = 98304;  l2 = 12; hw = 4096;  poff = 2621440; cstart = 24; toff4 = 6291456; }
    else if (q < 7340032) { tp = t3; chw = 32768;  l2 = 10; hw = 1024;  poff = 2752512; cstart = 48; toff4 = 7077888; }
    else                  { tp = t4; chw = 12288;  l2 = 8;  hw = 256;   poff = 2785280; cstart = 80; toff4 = 7340032; }
    int rem = (q - toff4) * 4;                         // element index within scale
    unsigned b = (unsigned)rem / (unsigned)chw;
    int r2   = rem - (int)b * chw;
    int c    = r2 >> l2;
    int hwid = r2 & (hw - 1);
    float catt = g_catt[b * 128 + cstart + c];
    float4 sv = *(const float4*)(g_sa + poff + (int)b * hw + hwid);
    float4 tv = *(const float4*)(tp + rem);
    float cp1 = 1.f + catt;
    float4 o;
    o.x = tv.x * (catt + sv.x * cp1);
    o.y = tv.y * (catt + sv.y * cp1);
    o.z = tv.z * (catt + sv.z * cp1);
    o.w = tv.w * (catt + sv.w * cp1);
    ((float4*)out)[q] = o;
}

// ---------------- launch ----------------
extern "C" void kernel_launch(void* const* d_in, const int* in_sizes, int n_in,
                              void* d_out, int out_size)
{
    const float* t0  = (const float*)d_in[0];
    const float* t1  = (const float*)d_in[1];
    const float* t2  = (const float*)d_in[2];
    const float* t3  = (const float*)d_in[3];
    const float* t4  = (const float*)d_in[4];
    const float* spw = (const float*)d_in[5];
    const float* spb = (const float*)d_in[6];
    const float* c1d = (const float*)d_in[7];
    const float* w0  = (const float*)d_in[8];  const float* bb0 = (const float*)d_in[9];
    const float* w1  = (const float*)d_in[10]; const float* bb1 = (const float*)d_in[11];
    const float* w2  = (const float*)d_in[12]; const float* bb2 = (const float*)d_in[13];
    const float* w3  = (const float*)d_in[14]; const float* bb3 = (const float*)d_in[15];
    const float* w4  = (const float*)d_in[16]; const float* bb4 = (const float*)d_in[17];
    float* out = (float*)d_out;

    k_chanreduce <<<2728, 256>>>(t0, t1, t2, t3, t4);
    k_spconv_pool<<<1408, 256>>>(spw, spb, t0, t1, t2, t3, t4);
    k_att        <<<32, 128>>>(c1d, w0, bb0, w1, bb1, w2, bb2, w3, bb3, w4, bb4);
    k_out        <<<29056, 256>>>(t0, t1, t2, t3, t4, out);
}

// round 4
// speedup vs baseline: 1.4249x; 1.4249x over previous
#include <cuda_runtime.h>
#include <math.h>

#define FULLMASK 0xFFFFFFFFu

// ---------------- scratch (device globals; allocation-free) ----------------
// global pixel index space: scales concatenated, PIXOFF = {0,2097152,2621440,2752512,2785280}, total 2793472
__device__ __align__(16) float g_amean[2793472];
__device__ __align__(16) float g_amax [2793472];
__device__ __align__(16) float g_sa   [2793472];
__device__ float g_part[32 * 128 * 16];   // per-(b,cg) chunk partial sums
__device__ float g_catt[32 * 128];        // channel attention per (b, cg)

__device__ __forceinline__ float sigmoidf_(float x) {
    return 1.0f / (1.0f + __expf(-x));
}

// ---------------- Kernel 1: channel mean/max per pixel ----------------
// one thread = 4 consecutive pixels (float4), grid exact: 698368 quads
__global__ __launch_bounds__(256) void k_chanreduce(
    const float* __restrict__ t0, const float* __restrict__ t1,
    const float* __restrict__ t2, const float* __restrict__ t3,
    const float* __restrict__ t4)
{
    int q = blockIdx.x * 256 + threadIdx.x;          // quad index
    int pix = q * 4;                                  // global pixel index
    const float* tp; int C, l2, hw, chw, poff;
    if (q < 524288)      { tp = t0; C = 8;  l2 = 16; hw = 65536; chw = 524288; poff = 0;       }
    else if (q < 655360) { tp = t1; C = 16; l2 = 14; hw = 16384; chw = 262144; poff = 2097152; }
    else if (q < 688128) { tp = t2; C = 24; l2 = 12; hw = 4096;  chw = 98304;  poff = 2621440; }
    else if (q < 696320) { tp = t3; C = 32; l2 = 10; hw = 1024;  chw = 32768;  poff = 2752512; }
    else                 { tp = t4; C = 48; l2 = 8;  hw = 256;   chw = 12288;  poff = 2785280; }
    int p    = pix - poff;
    int b    = p >> l2;
    int hwid = p & (hw - 1);
    const float4* base = (const float4*)(tp + (size_t)b * chw + hwid);
    int cs = hw >> 2;                                  // channel stride in float4s
    float4 v = base[0];
    float4 s = v, m = v;
    for (int c = 1; c < C; c++) {
        v = base[(size_t)c * cs];
        s.x += v.x; s.y += v.y; s.z += v.z; s.w += v.w;
        m.x = fmaxf(m.x, v.x); m.y = fmaxf(m.y, v.y);
        m.z = fmaxf(m.z, v.z); m.w = fmaxf(m.w, v.w);
    }
    float inv = 1.0f / (float)C;
    s.x *= inv; s.y *= inv; s.z *= inv; s.w *= inv;
    *(float4*)(g_amean + pix) = s;
    *(float4*)(g_amax  + pix) = m;
}

// ---------------- Kernel 2: dilated 7x7 conv (dil=3, pad=9) + sigmoid -> sa ----------------
// block = 256 threads, output tile 64(h) x 32(w); thread = 8 consecutive output rows, 1 col.
__global__ __launch_bounds__(256) void k_spconv(
    const float* __restrict__ spw, const float* __restrict__ spb)
{
    __shared__ float sm[82 * 50];
    __shared__ float sx[82 * 50];
    __shared__ float wsh[98];
    int bx = blockIdx.x;
    int HD, hw, poff, tw, per;
    if (bx < 1024)      { HD = 256; hw = 65536; poff = 0;       tw = 8; per = 32; }
    else if (bx < 1280) { HD = 128; hw = 16384; poff = 2097152; tw = 4; per = 8;  bx -= 1024; }
    else if (bx < 1344) { HD = 64;  hw = 4096;  poff = 2621440; tw = 2; per = 2;  bx -= 1280; }
    else if (bx < 1376) { HD = 32;  hw = 1024;  poff = 2752512; tw = 1; per = 1;  bx -= 1344; }
    else                { HD = 16;  hw = 256;   poff = 2785280; tw = 1; per = 1;  bx -= 1376; }
    int b = bx / per, r = bx % per;
    int tyb = r / tw, txb = r % tw;
    int y0 = tyb * 64, x0 = txb * 32;
    int tid = threadIdx.x;
    if (tid < 98) wsh[tid] = spw[tid];                 // [0..48]=mean w, [49..97]=max w
    int pb = poff + b * hw;
    for (int idx = tid; idx < 82 * 50; idx += 256) {
        int rr = idx / 50, cc = idx % 50;
        int gy = y0 - 9 + rr, gx = x0 - 9 + cc;
        float vm = 0.f, vx = 0.f;
        if ((unsigned)gy < (unsigned)HD && (unsigned)gx < (unsigned)HD) {
            int gi = pb + gy * HD + gx;
            vm = g_amean[gi]; vx = g_amax[gi];
        }
        sm[idx] = vm; sx[idx] = vx;
    }
    __syncthreads();

    int ty = tid >> 5, tx = tid & 31;                  // warp = one ty row-group
    int gx = x0 + tx;
    float acc[8];
#pragma unroll
    for (int d = 0; d < 8; d++) acc[d] = 0.f;
    int rbase = ty * 8;
#pragma unroll
    for (int kw = 0; kw < 7; kw++) {
        int cc = tx + 3 * kw;
        float cm[26], cx[26];
#pragma unroll
        for (int j = 0; j < 26; j++) {
            cm[j] = sm[(rbase + j) * 50 + cc];
            cx[j] = sx[(rbase + j) * 50 + cc];
        }
#pragma unroll
        for (int kh = 0; kh < 7; kh++) {
            float wm = wsh[kh * 7 + kw];
            float wx = wsh[49 + kh * 7 + kw];
#pragma unroll
            for (int d = 0; d < 8; d++)
                acc[d] += cm[d + 3 * kh] * wm + cx[d + 3 * kh] * wx;
        }
    }
    float bias = spb[0];
    if (gx < HD) {
#pragma unroll
        for (int d = 0; d < 8; d++) {
            int gy = y0 + rbase + d;
            if (gy < HD)
                g_sa[pb + gy * HD + gx] = sigmoidf_(acc[d] + bias);
        }
    }
}

// ---------------- Kernel 3: pooled partial sums of t*(1+sa) per (b, c) ----------------
// one block per (b, c, chunk<=4096 elems); deterministic two-stage reduce via g_part
__global__ __launch_bounds__(256) void k_pool(
    const float* __restrict__ t0, const float* __restrict__ t1,
    const float* __restrict__ t2, const float* __restrict__ t3,
    const float* __restrict__ t4)
{
    int bx = blockIdx.x;
    const float* tp; int Cc, cpp, hw, chw, poff, cstart;
    if (bx < 4096)      { tp = t0; Cc = 8;  cpp = 16; hw = 65536; chw = 524288; poff = 0;       cstart = 0;  }
    else if (bx < 6144) { tp = t1; Cc = 16; cpp = 4;  hw = 16384; chw = 262144; poff = 2097152; cstart = 8;  bx -= 4096; }
    else if (bx < 6912) { tp = t2; Cc = 24; cpp = 1;  hw = 4096;  chw = 98304;  poff = 2621440; cstart = 24; bx -= 6144; }
    else if (bx < 7936) { tp = t3; Cc = 32; cpp = 1;  hw = 1024;  chw = 32768;  poff = 2752512; cstart = 48; bx -= 6912; }
    else                { tp = t4; Cc = 48; cpp = 1;  hw = 256;   chw = 12288;  poff = 2785280; cstart = 80; bx -= 7936; }
    int b  = bx / (Cc * cpp);
    int r  = bx % (Cc * cpp);
    int c  = r / cpp;
    int ch = r % cpp;
    int n  = hw < 4096 ? hw : 4096;
    int start = ch * 4096;
    const float4* tb = (const float4*)(tp + (size_t)b * chw + (size_t)c * hw + start);
    const float4* sb = (const float4*)(g_sa + poff + b * hw + start);
    int tid = threadIdx.x;
    float sum = 0.f;
    for (int i = tid; i * 4 < n; i += 256) {
        float4 tv = tb[i], sv = sb[i];
        sum += tv.x * (1.f + sv.x) + tv.y * (1.f + sv.y)
             + tv.z * (1.f + sv.z) + tv.w * (1.f + sv.w);
    }
    for (int o = 16; o; o >>= 1) sum += __shfl_down_sync(FULLMASK, sum, o);
    __shared__ float ws[8];
    if ((tid & 31) == 0) ws[tid >> 5] = sum;
    __syncthreads();
    if (tid == 0) {
        float tot = 0.f;
#pragma unroll
        for (int w2 = 0; w2 < 8; w2++) tot += ws[w2];
        g_part[(b * 128 + cstart + c) * 16 + ch] = tot;
    }
}

// ---------------- Kernel 4: 1D conv over pooled + per-scale FC + sigmoid -> catt ----------------
// one block per b (128 threads). Stage 1: pooled+1dconv into smem.
// Stage 2: 4 warps x 32 dots; each dot is lane-strided over k (coalesced w rows),
// ash cached in 4 regs per lane, 5-shuffle butterfly reduce.
__global__ __launch_bounds__(128) void k_att(
    const float* __restrict__ c1d,
    const float* __restrict__ w0, const float* __restrict__ bb0,
    const float* __restrict__ w1, const float* __restrict__ bb1,
    const float* __restrict__ w2, const float* __restrict__ bb2,
    const float* __restrict__ w3, const float* __restrict__ bb3,
    const float* __restrict__ w4, const float* __restrict__ bb4)
{
    int b = blockIdx.x;
    int j = threadIdx.x;
    // ---- stage 1: pooled value for channel j ----
    int cpp, hw;
    if (j < 8)       { cpp = 16; hw = 65536; }
    else if (j < 24) { cpp = 4;  hw = 16384; }
    else if (j < 48) { cpp = 1;  hw = 4096;  }
    else if (j < 80) { cpp = 1;  hw = 1024;  }
    else             { cpp = 1;  hw = 256;   }
    float pv = 0.f;
    for (int k = 0; k < cpp; k++) pv += g_part[(b * 128 + j) * 16 + k];
    pv /= (float)hw;
    __shared__ float psh[128];
    __shared__ __align__(16) float ash[128];
    psh[j] = pv;
    __syncthreads();
    float a = c1d[1] * psh[j];
    if (j > 0)   a += c1d[0] * psh[j - 1];
    if (j < 127) a += c1d[2] * psh[j + 1];
    ash[j] = a;
    __syncthreads();

    // ---- stage 2: 4 warps x 32 dots ----
    int wid = j >> 5, lid = j & 31;
    // cache ash in 4 regs per lane (k = lid + 32m)
    float x0_ = ash[lid], x1_ = ash[lid + 32], x2_ = ash[lid + 64], x3_ = ash[lid + 96];
    for (int jj = wid * 32; jj < wid * 32 + 32; jj++) {
        const float* wp; const float* bp; int c_;
        if (jj < 8)       { wp = w0; bp = bb0; c_ = jj;      }
        else if (jj < 24) { wp = w1; bp = bb1; c_ = jj - 8;  }
        else if (jj < 48) { wp = w2; bp = bb2; c_ = jj - 24; }
        else if (jj < 80) { wp = w3; bp = bb3; c_ = jj - 48; }
        else              { wp = w4; bp = bb4; c_ = jj - 80; }
        const float* wr = wp + c_ * 128 + lid;
        float d = wr[0] * x0_ + wr[32] * x1_ + wr[64] * x2_ + wr[96] * x3_;
#pragma unroll
        for (int o = 16; o; o >>= 1) d += __shfl_xor_sync(FULLMASK, d, o);
        if (lid == 0)
            g_catt[b * 128 + jj] = sigmoidf_(d + bp[c_]);
    }
}

// ---------------- Kernel 5: out = t * (catt + sa*(1+catt)) ----------------
__global__ __launch_bounds__(256) void k_out(
    const float* __restrict__ t0, const float* __restrict__ t1,
    const float* __restrict__ t2, const float* __restrict__ t3,
    const float* __restrict__ t4, float* __restrict__ out)
{
    int q = blockIdx.x * 256 + threadIdx.x;            // quad index, exact 7438336
    const float* tp; int chw, l2, hw, poff, cstart, toff4, sh, m3;
    if (q < 4194304)      { tp = t0; chw = 524288; l2 = 16; hw = 65536; poff = 0;       cstart = 0;  toff4 = 0;       sh = 19; m3 = 0; }
    else if (q < 6291456) { tp = t1; chw = 262144; l2 = 14; hw = 16384; poff = 2097152; cstart = 8;  toff4 = 4194304; sh = 18; m3 = 0; }
    else if (q < 7077888) { tp = t2; chw = 98304;  l2 = 12; hw = 4096;  poff = 2621440; cstart = 24; toff4 = 6291456; sh = 15; m3 = 1; }
    else if (q < 7340032) { tp = t3; chw = 32768;  l2 = 10; hw = 1024;  poff = 2752512; cstart = 48; toff4 = 7077888; sh = 15; m3 = 0; }
    else                  { tp = t4; chw = 12288;  l2 = 8;  hw = 256;   poff = 2785280; cstart = 80; toff4 = 7340032; sh = 12; m3 = 1; }
    int rem = (q - toff4) * 4;                         // element index within scale
    unsigned b = (unsigned)rem >> sh;                  // rem / chw via shift (+ /3 when m3)
    if (m3) b = __umulhi(b, 0xAAAAAAABu) >> 1;
    int r2   = rem - (int)b * chw;
    int c    = r2 >> l2;
    int hwid = r2 & (hw - 1);
    float catt = g_catt[b * 128 + cstart + c];
    float4 sv = *(const float4*)(g_sa + poff + (int)b * hw + hwid);
    float4 tv = *(const float4*)(tp + rem);
    float cp1 = 1.f + catt;
    float4 o;
    o.x = tv.x * (catt + sv.x * cp1);
    o.y = tv.y * (catt + sv.y * cp1);
    o.z = tv.z * (catt + sv.z * cp1);
    o.w = tv.w * (catt + sv.w * cp1);
    ((float4*)out)[q] = o;
}

// ---------------- launch ----------------
extern "C" void kernel_launch(void* const* d_in, const int* in_sizes, int n_in,
                              void* d_out, int out_size)
{
    const float* t0  = (const float*)d_in[0];
    const float* t1  = (const float*)d_in[1];
    const float* t2  = (const float*)d_in[2];
    const float* t3  = (const float*)d_in[3];
    const float* t4  = (const float*)d_in[4];
    const float* spw = (const float*)d_in[5];
    const float* spb = (const float*)d_in[6];
    const float* c1d = (const float*)d_in[7];
    const float* w0  = (const float*)d_in[8];  const float* bb0 = (const float*)d_in[9];
    const float* w1  = (const float*)d_in[10]; const float* bb1 = (const float*)d_in[11];
    const float* w2  = (const float*)d_in[12]; const float* bb2 = (const float*)d_in[13];
    const float* w3  = (const float*)d_in[14]; const float* bb3 = (const float*)d_in[15];
    const float* w4  = (const float*)d_in[16]; const float* bb4 = (const float*)d_in[17];
    float* out = (float*)d_out;

    k_chanreduce<<<2728, 256>>>(t0, t1, t2, t3, t4);
    k_spconv   <<<1408, 256>>>(spw, spb);
    k_pool     <<<9472, 256>>>(t0, t1, t2, t3, t4);
    k_att      <<<32, 128>>>(c1d, w0, bb0, w1, bb1, w2, bb2, w3, bb3, w4, bb4);
    k_out      <<<29056, 256>>>(t0, t1, t2, t3, t4, out);
}

// round 5
// speedup vs baseline: 1.5997x; 1.1227x over previous
#include <cuda_runtime.h>
#include <cuda_fp16.h>
#include <math.h>

#define FULLMASK 0xFFFFFFFFu

// ---------------- scratch (device globals; allocation-free) ----------------
// global pixel index space: scales concatenated, PIXOFF = {0,2097152,2621440,2752512,2785280}, total 2793472
__device__ __align__(16) __half g_ameanh[2793472];
__device__ __align__(16) __half g_amaxh [2793472];
__device__ __align__(16) float  g_sa    [2793472];
__device__ float g_part[32 * 128 * 16];   // per-(b,cg) chunk partial sums
__device__ float g_catt[32 * 128];        // channel attention per (b, cg)

__device__ __forceinline__ float sigmoidf_(float x) {
    return 1.0f / (1.0f + __expf(-x));
}

// ---------------- Kernel 1: channel mean/max per pixel (fp16 outputs) ----------------
// one thread = 4 consecutive pixels (float4), grid exact: 698368 quads
__global__ __launch_bounds__(256) void k_chanreduce(
    const float* __restrict__ t0, const float* __restrict__ t1,
    const float* __restrict__ t2, const float* __restrict__ t3,
    const float* __restrict__ t4)
{
    int q = blockIdx.x * 256 + threadIdx.x;          // quad index
    int pix = q * 4;                                  // global pixel index
    const float* tp; int C, l2, hw, chw, poff;
    if (q < 524288)      { tp = t0; C = 8;  l2 = 16; hw = 65536; chw = 524288; poff = 0;       }
    else if (q < 655360) { tp = t1; C = 16; l2 = 14; hw = 16384; chw = 262144; poff = 2097152; }
    else if (q < 688128) { tp = t2; C = 24; l2 = 12; hw = 4096;  chw = 98304;  poff = 2621440; }
    else if (q < 696320) { tp = t3; C = 32; l2 = 10; hw = 1024;  chw = 32768;  poff = 2752512; }
    else                 { tp = t4; C = 48; l2 = 8;  hw = 256;   chw = 12288;  poff = 2785280; }
    int p    = pix - poff;
    int b    = p >> l2;
    int hwid = p & (hw - 1);
    const float4* base = (const float4*)(tp + (size_t)b * chw + hwid);
    int cs = hw >> 2;                                  // channel stride in float4s
    float4 v = base[0];
    float4 s = v, m = v;
    for (int c = 1; c < C; c++) {
        v = base[(size_t)c * cs];
        s.x += v.x; s.y += v.y; s.z += v.z; s.w += v.w;
        m.x = fmaxf(m.x, v.x); m.y = fmaxf(m.y, v.y);
        m.z = fmaxf(m.z, v.z); m.w = fmaxf(m.w, v.w);
    }
    float inv = 1.0f / (float)C;
    half2 s01 = __floats2half2_rn(s.x * inv, s.y * inv);
    half2 s23 = __floats2half2_rn(s.z * inv, s.w * inv);
    half2 m01 = __floats2half2_rn(m.x, m.y);
    half2 m23 = __floats2half2_rn(m.z, m.w);
    *(half2*)(g_ameanh + pix)     = s01;
    *(half2*)(g_ameanh + pix + 2) = s23;
    *(half2*)(g_amaxh  + pix)     = m01;
    *(half2*)(g_amaxh  + pix + 2) = m23;
}

// ---------------- Kernel 2: dilated 7x7 conv (dil=3, pad=9) + sigmoid -> sa ----------------
// block = 256 threads, output tile 64(h) x 32(w); thread = 8 consecutive output rows, 1 col.
__global__ __launch_bounds__(256) void k_spconv(
    const float* __restrict__ spw, const float* __restrict__ spb)
{
    __shared__ float sm[82 * 50];
    __shared__ float sx[82 * 50];
    __shared__ float wsh[98];
    int bx = blockIdx.x;
    int HD, hw, poff, tw, per;
    if (bx < 1024)      { HD = 256; hw = 65536; poff = 0;       tw = 8; per = 32; }
    else if (bx < 1280) { HD = 128; hw = 16384; poff = 2097152; tw = 4; per = 8;  bx -= 1024; }
    else if (bx < 1344) { HD = 64;  hw = 4096;  poff = 2621440; tw = 2; per = 2;  bx -= 1280; }
    else if (bx < 1376) { HD = 32;  hw = 1024;  poff = 2752512; tw = 1; per = 1;  bx -= 1344; }
    else                { HD = 16;  hw = 256;   poff = 2785280; tw = 1; per = 1;  bx -= 1376; }
    int b = bx / per, r = bx % per;
    int tyb = r / tw, txb = r % tw;
    int y0 = tyb * 64, x0 = txb * 32;
    int tid = threadIdx.x;
    if (tid < 98) wsh[tid] = spw[tid];                 // [0..48]=mean w, [49..97]=max w
    int pb = poff + b * hw;
    for (int idx = tid; idx < 82 * 50; idx += 256) {
        int rr = idx / 50, cc = idx % 50;
        int gy = y0 - 9 + rr, gx = x0 - 9 + cc;
        float vm = 0.f, vx = 0.f;
        if ((unsigned)gy < (unsigned)HD && (unsigned)gx < (unsigned)HD) {
            int gi = pb + gy * HD + gx;
            vm = __half2float(g_ameanh[gi]);
            vx = __half2float(g_amaxh [gi]);
        }
        sm[idx] = vm; sx[idx] = vx;
    }
    __syncthreads();

    int ty = tid >> 5, tx = tid & 31;                  // warp = one ty row-group
    int gx = x0 + tx;
    float acc[8];
#pragma unroll
    for (int d = 0; d < 8; d++) acc[d] = 0.f;
    int rbase = ty * 8;
#pragma unroll
    for (int kw = 0; kw < 7; kw++) {
        int cc = tx + 3 * kw;
        float cm[26], cx[26];
#pragma unroll
        for (int j = 0; j < 26; j++) {
            cm[j] = sm[(rbase + j) * 50 + cc];
            cx[j] = sx[(rbase + j) * 50 + cc];
        }
#pragma unroll
        for (int kh = 0; kh < 7; kh++) {
            float wm = wsh[kh * 7 + kw];
            float wx = wsh[49 + kh * 7 + kw];
#pragma unroll
            for (int d = 0; d < 8; d++)
                acc[d] += cm[d + 3 * kh] * wm + cx[d + 3 * kh] * wx;
        }
    }
    float bias = spb[0];
    if (gx < HD) {
#pragma unroll
        for (int d = 0; d < 8; d++) {
            int gy = y0 + rbase + d;
            if (gy < HD)
                g_sa[pb + gy * HD + gx] = sigmoidf_(acc[d] + bias);
        }
    }
}

// ---------------- Kernel 3: pooled partial sums of t*(1+sa) per (b, c) ----------------
// one block per (b, c, chunk<=4096 elems); deterministic two-stage reduce via g_part
__global__ __launch_bounds__(256) void k_pool(
    const float* __restrict__ t0, const float* __restrict__ t1,
    const float* __restrict__ t2, const float* __restrict__ t3,
    const float* __restrict__ t4)
{
    int bx = blockIdx.x;
    const float* tp; int Cc, cpp, hw, chw, poff, cstart;
    if (bx < 4096)      { tp = t0; Cc = 8;  cpp = 16; hw = 65536; chw = 524288; poff = 0;       cstart = 0;  }
    else if (bx < 6144) { tp = t1; Cc = 16; cpp = 4;  hw = 16384; chw = 262144; poff = 2097152; cstart = 8;  bx -= 4096; }
    else if (bx < 6912) { tp = t2; Cc = 24; cpp = 1;  hw = 4096;  chw = 98304;  poff = 2621440; cstart = 24; bx -= 6144; }
    else if (bx < 7936) { tp = t3; Cc = 32; cpp = 1;  hw = 1024;  chw = 32768;  poff = 2752512; cstart = 48; bx -= 6912; }
    else                { tp = t4; Cc = 48; cpp = 1;  hw = 256;   chw = 12288;  poff = 2785280; cstart = 80; bx -= 7936; }
    int b  = bx / (Cc * cpp);
    int r  = bx % (Cc * cpp);
    int c  = r / cpp;
    int ch = r % cpp;
    int n  = hw < 4096 ? hw : 4096;
    int start = ch * 4096;
    const float4* tb = (const float4*)(tp + (size_t)b * chw + (size_t)c * hw + start);
    const float4* sb = (const float4*)(g_sa + poff + b * hw + start);
    int tid = threadIdx.x;
    float sum = 0.f;
    for (int i = tid; i * 4 < n; i += 256) {
        float4 tv = tb[i], sv = sb[i];
        sum += tv.x * (1.f + sv.x) + tv.y * (1.f + sv.y)
             + tv.z * (1.f + sv.z) + tv.w * (1.f + sv.w);
    }
    for (int o = 16; o; o >>= 1) sum += __shfl_down_sync(FULLMASK, sum, o);
    __shared__ float ws[8];
    if ((tid & 31) == 0) ws[tid >> 5] = sum;
    __syncthreads();
    if (tid == 0) {
        float tot = 0.f;
#pragma unroll
        for (int w2 = 0; w2 < 8; w2++) tot += ws[w2];
        g_part[(b * 128 + cstart + c) * 16 + ch] = tot;
    }
}

// ---------------- Kernel 4: 1D conv over pooled + per-scale FC + sigmoid -> catt ----------------
// fully-unrolled float4 dot with 4 independent accumulators (MLP ~32) — proven R2 version
__global__ __launch_bounds__(128) void k_att(
    const float* __restrict__ c1d,
    const float* __restrict__ w0, const float* __restrict__ bb0,
    const float* __restrict__ w1, const float* __restrict__ bb1,
    const float* __restrict__ w2, const float* __restrict__ bb2,
    const float* __restrict__ w3, const float* __restrict__ bb3,
    const float* __restrict__ w4, const float* __restrict__ bb4)
{
    int b = blockIdx.x;
    int j = threadIdx.x;
    int cpp, hw, c_; const float* wp; const float* bp;
    if (j < 8)       { cpp = 16; hw = 65536; wp = w0; bp = bb0; c_ = j;      }
    else if (j < 24) { cpp = 4;  hw = 16384; wp = w1; bp = bb1; c_ = j - 8;  }
    else if (j < 48) { cpp = 1;  hw = 4096;  wp = w2; bp = bb2; c_ = j - 24; }
    else if (j < 80) { cpp = 1;  hw = 1024;  wp = w3; bp = bb3; c_ = j - 48; }
    else             { cpp = 1;  hw = 256;   wp = w4; bp = bb4; c_ = j - 80; }
    float pv = 0.f;
    for (int k = 0; k < cpp; k++) pv += g_part[(b * 128 + j) * 16 + k];
    pv /= (float)hw;
    __shared__ float psh[128];
    __shared__ __align__(16) float ash[128];
    psh[j] = pv;
    __syncthreads();
    float a = c1d[1] * psh[j];
    if (j > 0)   a += c1d[0] * psh[j - 1];
    if (j < 127) a += c1d[2] * psh[j + 1];
    ash[j] = a;
    __syncthreads();

    const float4* wv = (const float4*)(wp + c_ * 128);
    const float4* av = (const float4*)ash;
    float s0 = 0.f, s1 = 0.f, s2 = 0.f, s3 = 0.f;
#pragma unroll
    for (int k = 0; k < 32; k += 4) {
        float4 wa = wv[k + 0], wb = wv[k + 1], wc = wv[k + 2], wd = wv[k + 3];
        float4 xa = av[k + 0], xb = av[k + 1], xc = av[k + 2], xd = av[k + 3];
        s0 += wa.x * xa.x + wa.y * xa.y + wa.z * xa.z + wa.w * xa.w;
        s1 += wb.x * xb.x + wb.y * xb.y + wb.z * xb.z + wb.w * xb.w;
        s2 += wc.x * xc.x + wc.y * xc.y + wc.z * xc.z + wc.w * xc.w;
        s3 += wd.x * xd.x + wd.y * xd.y + wd.z * xd.z + wd.w * xd.w;
    }
    float dot = bp[c_] + ((s0 + s1) + (s2 + s3));
    g_catt[b * 128 + j] = sigmoidf_(dot);
}

// ---------------- Kernel 5: out = t * (catt + sa*(1+catt)) ----------------
__global__ __launch_bounds__(256) void k_out(
    const float* __restrict__ t0, const float* __restrict__ t1,
    const float* __restrict__ t2, const float* __restrict__ t3,
    const float* __restrict__ t4, float* __restrict__ out)
{
    int q = blockIdx.x * 256 + threadIdx.x;            // quad index, exact 7438336
    const float* tp; int chw, l2, hw, poff, cstart, toff4, sh, m3;
    if (q < 4194304)      { tp = t0; chw = 524288; l2 = 16; hw = 65536; poff = 0;       cstart = 0;  toff4 = 0;       sh = 19; m3 = 0; }
    else if (q < 6291456) { tp = t1; chw = 262144; l2 = 14; hw = 16384; poff = 2097152; cstart = 8;  toff4 = 4194304; sh = 18; m3 = 0; }
    else if (q < 7077888) { tp = t2; chw = 98304;  l2 = 12; hw = 4096;  poff = 2621440; cstart = 24; toff4 = 6291456; sh = 15; m3 = 1; }
    else if (q < 7340032) { tp = t3; chw = 32768;  l2 = 10; hw = 1024;  poff = 2752512; cstart = 48; toff4 = 7077888; sh = 15; m3 = 0; }
    else                  { tp = t4; chw = 12288;  l2 = 8;  hw = 256;   poff = 2785280; cstart = 80; toff4 = 7340032; sh = 12; m3 = 1; }
    int rem = (q - toff4) * 4;                         // element index within scale
    unsigned b = (unsigned)rem >> sh;                  // rem / chw via shift (+ /3 when m3)
    if (m3) b = __umulhi(b, 0xAAAAAAABu) >> 1;
    int r2   = rem - (int)b * chw;
    int c    = r2 >> l2;
    int hwid = r2 & (hw - 1);
    float catt = g_catt[b * 128 + cstart + c];
    float4 sv = *(const float4*)(g_sa + poff + (int)b * hw + hwid);
    float4 tv = *(const float4*)(tp + rem);
    float cp1 = 1.f + catt;
    float4 o;
    o.x = tv.x * (catt + sv.x * cp1);
    o.y = tv.y * (catt + sv.y * cp1);
    o.z = tv.z * (catt + sv.z * cp1);
    o.w = tv.w * (catt + sv.w * cp1);
    ((float4*)out)[q] = o;
}

// ---------------- launch ----------------
extern "C" void kernel_launch(void* const* d_in, const int* in_sizes, int n_in,
                              void* d_out, int out_size)
{
    const float* t0  = (const float*)d_in[0];
    const float* t1  = (const float*)d_in[1];
    const float* t2  = (const float*)d_in[2];
    const float* t3  = (const float*)d_in[3];
    const float* t4  = (const float*)d_in[4];
    const float* spw = (const float*)d_in[5];
    const float* spb = (const float*)d_in[6];
    const float* c1d = (const float*)d_in[7];
    const float* w0  = (const float*)d_in[8];  const float* bb0 = (const float*)d_in[9];
    const float* w1  = (const float*)d_in[10]; const float* bb1 = (const float*)d_in[11];
    const float* w2  = (const float*)d_in[12]; const float* bb2 = (const float*)d_in[13];
    const float* w3  = (const float*)d_in[14]; const float* bb3 = (const float*)d_in[15];
    const float* w4  = (const float*)d_in[16]; const float* bb4 = (const float*)d_in[17];
    float* out = (float*)d_out;

    k_chanreduce<<<2728, 256>>>(t0, t1, t2, t3, t4);
    k_spconv   <<<1408, 256>>>(spw, spb);
    k_pool     <<<9472, 256>>>(t0, t1, t2, t3, t4);
    k_att      <<<32, 128>>>(c1d, w0, bb0, w1, bb1, w2, bb2, w3, bb3, w4, bb4);
    k_out      <<<29056, 256>>>(t0, t1, t2, t3, t4, out);
}